// round 16
// baseline (speedup 1.0000x reference)
#include <cuda_runtime.h>
#include <cuda_bf16.h>

#define H_IMG 96
#define W_IMG 96
#define C_IMG 1024
#define CV    (C_IMG / 4)   // 256 float4 per pixel
#define POOL  7
#define NUM_ROIS 600

// One CTA per (py, roi). 128 threads; thread t owns float4 slots t and t+128.
// The 14 per-thread outputs (7 px x 2 channel-groups) form a software-pipelined
// task chain: while combining/storing task i, task i+1's 4 loads are in flight.
// Peak live data = cur(16) + nxt(16) = 32 regs -> fits the (128,10) 51-reg
// budget, keeping R10's occupancy while hiding ~200 cyc of load latency.
__global__ __launch_bounds__(128, 10)
void roi_pool_kernel(const float* __restrict__ img,
                     const int*   __restrict__ rois,
                     float*       __restrict__ out) {
    const int py  = blockIdx.x;        // 0..6
    const int roi = blockIdx.y;        // 0..599

    __shared__ int   so0[POOL], so1[POOL];   // col offsets in float4 units
    __shared__ float sfx[POOL];
    __shared__ int   srow[2];                // r0, r1 pixel-row offsets
    __shared__ float sfy;

    if (threadIdx.x < POOL) {
        const int4 rr = __ldg(reinterpret_cast<const int4*>(rois) + roi);
        const int x = rr.x;
        const int y = rr.y;
        const int w = max(rr.z, 1);
        const int h = max(rr.w, 1);
        const int i = threadIdx.x;

        // horizontal for px = i (TF1 semantics: src = dst * in/out)
        const float in_x = (float)i * ((float)w / (float)POOL);
        const int   x0   = (int)in_x;
        const int   x1   = min(x0 + 1, w - 1);
        const float fx   = in_x - (float)x0;
        const int   c0   = min(max(x + x0, 0), W_IMG - 1);
        int         c1   = min(max(x + x1, 0), W_IMG - 1);
        if (fx == 0.0f) c1 = c0;          // zero-weight dedup -> L1 hit
        so0[i] = c0 * CV;
        so1[i] = c1 * CV;
        sfx[i] = fx;

        if (i == 0) {
            const float in_y = (float)py * ((float)h / (float)POOL);
            const int   y0   = (int)in_y;
            const int   y1   = min(y0 + 1, h - 1);
            const float fy   = in_y - (float)y0;
            const int   r0   = min(max(y + y0, 0), H_IMG - 1);
            int         r1   = min(max(y + y1, 0), H_IMG - 1);
            if (fy == 0.0f) r1 = r0;      // zero-weight dedup
            srow[0] = r0 * W_IMG;
            srow[1] = r1 * W_IMG;
            sfy = fy;
        }
    }
    __syncthreads();

    const int t = threadIdx.x;   // 0..127
    const float fy = sfy;
    const float gy = 1.0f - fy;

    const float4* __restrict__ row0 =
        reinterpret_cast<const float4*>(img) + (size_t)srow[0] * CV + t;
    const float4* __restrict__ row1 =
        reinterpret_cast<const float4*>(img) + (size_t)srow[1] * CV + t;

    float4* __restrict__ o = reinterpret_cast<float4*>(out)
        + ((size_t)roi * (POOL * POOL) + (size_t)py * POOL) * CV + t;

    // ---- software pipeline over 14 tasks: (px,A),(px,B) for px = 0..6 ----
    // cur/nxt are one 4-corner group each (16 regs apiece).
    float4 c00, c01, c10, c11;   // current task's corners
    {
        const int q0 = so0[0], q1 = so1[0];
        c00 = __ldg(row0 + q0);
        c01 = __ldg(row0 + q1);
        c10 = __ldg(row1 + q0);
        c11 = __ldg(row1 + q1);
    }

    #pragma unroll 1
    for (int px = 0; px < POOL; ++px) {
        const int   q0 = so0[px];
        const int   q1 = so1[px];
        const float fx = sfx[px];
        const float w00 = (1.0f - fx) * gy;
        const float w01 = fx * gy;
        const float w10 = (1.0f - fx) * fy;
        const float w11 = fx * fy;

        // --- task A(px): prefetch B(px) (slots +128, same columns) ---
        float4 n00 = __ldg(row0 + q0 + 128);
        float4 n01 = __ldg(row0 + q1 + 128);
        float4 n10 = __ldg(row1 + q0 + 128);
        float4 n11 = __ldg(row1 + q1 + 128);

        float4 ra;
        ra.x = c00.x * w00 + c01.x * w01 + c10.x * w10 + c11.x * w11;
        ra.y = c00.y * w00 + c01.y * w01 + c10.y * w10 + c11.y * w11;
        ra.z = c00.z * w00 + c01.z * w01 + c10.z * w10 + c11.z * w11;
        ra.w = c00.w * w00 + c01.w * w01 + c10.w * w10 + c11.w * w11;
        o[px * CV] = ra;

        c00 = n00; c01 = n01; c10 = n10; c11 = n11;

        // --- task B(px): prefetch A(px+1) ---
        if (px < POOL - 1) {
            const int p0 = so0[px + 1];
            const int p1 = so1[px + 1];
            n00 = __ldg(row0 + p0);
            n01 = __ldg(row0 + p1);
            n10 = __ldg(row1 + p0);
            n11 = __ldg(row1 + p1);
        }

        float4 rb;
        rb.x = c00.x * w00 + c01.x * w01 + c10.x * w10 + c11.x * w11;
        rb.y = c00.y * w00 + c01.y * w01 + c10.y * w10 + c11.y * w11;
        rb.z = c00.z * w00 + c01.z * w01 + c10.z * w10 + c11.z * w11;
        rb.w = c00.w * w00 + c01.w * w01 + c10.w * w10 + c11.w * w11;
        o[px * CV + 128] = rb;

        c00 = n00; c01 = n01; c10 = n10; c11 = n11;
    }
}

extern "C" void kernel_launch(void* const* d_in, const int* in_sizes, int n_in,
                              void* d_out, int out_size) {
    const float* img  = (const float*)d_in[0];
    const int*   rois = (const int*)d_in[1];
    float*       out  = (float*)d_out;

    dim3 grid(POOL, NUM_ROIS);
    roi_pool_kernel<<<grid, 128>>>(img, rois, out);
}

// round 17
// speedup vs baseline: 1.0544x; 1.0544x over previous
#include <cuda_runtime.h>
#include <cuda_bf16.h>

#define H_IMG 96
#define W_IMG 96
#define C_IMG 1024
#define CV    (C_IMG / 4)   // 256 float4 per pixel
#define POOL  7
#define NUM_ROIS 600

// R10 design (best measured) + streaming stores: one CTA per (py, roi),
// 128 threads, thread t owns float4 slots t and t+128, rolled px loop with
// the 8x LDG.128 batch. Output is written with __stwt (write-through /
// no-allocate) so the 120 MB output stream does not thrash L2, keeping the
// 37.7 MB image L2-resident and cutting DRAM re-reads.
__global__ __launch_bounds__(128, 10)
void roi_pool_kernel(const float* __restrict__ img,
                     const int*   __restrict__ rois,
                     float*       __restrict__ out) {
    const int py  = blockIdx.x;        // 0..6
    const int roi = blockIdx.y;        // 0..599

    __shared__ int   so0[POOL], so1[POOL];   // col offsets in float4 units
    __shared__ float sfx[POOL];
    __shared__ int   srow[2];                // r0, r1 pixel-row offsets
    __shared__ float sfy;

    if (threadIdx.x < POOL) {
        const int4 rr = __ldg(reinterpret_cast<const int4*>(rois) + roi);
        const int x = rr.x;
        const int y = rr.y;
        const int w = max(rr.z, 1);
        const int h = max(rr.w, 1);
        const int i = threadIdx.x;

        // horizontal for px = i (TF1 semantics: src = dst * in/out)
        const float in_x = (float)i * ((float)w / (float)POOL);
        const int   x0   = (int)in_x;
        const int   x1   = min(x0 + 1, w - 1);
        const float fx   = in_x - (float)x0;
        const int   c0   = min(max(x + x0, 0), W_IMG - 1);
        int         c1   = min(max(x + x1, 0), W_IMG - 1);
        if (fx == 0.0f) c1 = c0;          // zero-weight dedup -> L1 hit
        so0[i] = c0 * CV;
        so1[i] = c1 * CV;
        sfx[i] = fx;

        if (i == 0) {
            const float in_y = (float)py * ((float)h / (float)POOL);
            const int   y0   = (int)in_y;
            const int   y1   = min(y0 + 1, h - 1);
            const float fy   = in_y - (float)y0;
            const int   r0   = min(max(y + y0, 0), H_IMG - 1);
            int         r1   = min(max(y + y1, 0), H_IMG - 1);
            if (fy == 0.0f) r1 = r0;      // zero-weight dedup
            srow[0] = r0 * W_IMG;
            srow[1] = r1 * W_IMG;
            sfy = fy;
        }
    }
    __syncthreads();

    const int t = threadIdx.x;   // 0..127
    const float fy = sfy;
    const float gy = 1.0f - fy;

    const float4* __restrict__ row0 =
        reinterpret_cast<const float4*>(img) + (size_t)srow[0] * CV + t;
    const float4* __restrict__ row1 =
        reinterpret_cast<const float4*>(img) + (size_t)srow[1] * CV + t;

    float4* __restrict__ o = reinterpret_cast<float4*>(out)
        + ((size_t)roi * (POOL * POOL) + (size_t)py * POOL) * CV + t;

    #pragma unroll 1
    for (int px = 0; px < POOL; ++px) {
        const int   o0 = so0[px];
        const int   o1 = so1[px];
        const float fx = sfx[px];

        // 8 independent LDG.128 batched before any dependent math
        const float4 a0 = __ldg(row0 + o0);
        const float4 b0 = __ldg(row0 + o1);
        const float4 c0v = __ldg(row1 + o0);
        const float4 d0 = __ldg(row1 + o1);
        const float4 a1 = __ldg(row0 + o0 + 128);
        const float4 b1 = __ldg(row0 + o1 + 128);
        const float4 c1v = __ldg(row1 + o0 + 128);
        const float4 d1 = __ldg(row1 + o1 + 128);

        const float w00 = (1.0f - fx) * gy;
        const float w01 = fx * gy;
        const float w10 = (1.0f - fx) * fy;
        const float w11 = fx * fy;

        float4 r0v, r1v;
        r0v.x = a0.x * w00 + b0.x * w01 + c0v.x * w10 + d0.x * w11;
        r0v.y = a0.y * w00 + b0.y * w01 + c0v.y * w10 + d0.y * w11;
        r0v.z = a0.z * w00 + b0.z * w01 + c0v.z * w10 + d0.z * w11;
        r0v.w = a0.w * w00 + b0.w * w01 + c0v.w * w10 + d0.w * w11;

        r1v.x = a1.x * w00 + b1.x * w01 + c1v.x * w10 + d1.x * w11;
        r1v.y = a1.y * w00 + b1.y * w01 + c1v.y * w10 + d1.y * w11;
        r1v.z = a1.z * w00 + b1.z * w01 + c1v.z * w10 + d1.z * w11;
        r1v.w = a1.w * w00 + b1.w * w01 + c1v.w * w10 + d1.w * w11;

        // streaming stores: bypass/evict-first in L2, output never read again
        __stwt(o + px * CV,       r0v);
        __stwt(o + px * CV + 128, r1v);
    }
}

extern "C" void kernel_launch(void* const* d_in, const int* in_sizes, int n_in,
                              void* d_out, int out_size) {
    const float* img  = (const float*)d_in[0];
    const int*   rois = (const int*)d_in[1];
    float*       out  = (float*)d_out;

    dim3 grid(POOL, NUM_ROIS);
    roi_pool_kernel<<<grid, 128>>>(img, rois, out);
}